// round 10
// baseline (speedup 1.0000x reference)
#include <cuda_runtime.h>

// Problem constants
#define BB     8
#define NN     2048
#define DF     256     // d_feat
#define KF     257     // d_feat + 1
#define DH     64      // head dim
#define QKW    128     // q(64) | k(64) packed per row

// ---------------- scratch (__device__ globals; no allocation) ----------------
__device__ float g_QK[(size_t)BB * NN * QKW];          // 8 MB: [row][0..63]=q, [64..127]=k
__device__ float g_cs_part[(size_t)BB * 16 * NN];      // per-(b, n-tile) column-sum partials
__device__ float g_cs[(size_t)BB * NN];                // final column sums
__device__ float g_y_part[(size_t)BB * 16 * NN * 3];   // per-(b, n-chunk) y partials

// ---------------- f32x2 helpers ----------------
__device__ __forceinline__ void ffma2(unsigned long long& acc,
                                      unsigned long long a,
                                      unsigned long long b)
{
    asm("fma.rn.f32x2 %0, %1, %2, %0;" : "+l"(acc) : "l"(a), "l"(b));
}
__device__ __forceinline__ float2 u2f(unsigned long long v)
{
    float2 r;
    asm("mov.b64 {%0,%1}, %2;" : "=f"(r.x), "=f"(r.y) : "l"(v));
    return r;
}

// =============================================================================
// K1: fc = [f | log_eps] ; QK[row] = fc @ [W_q | W_k]   (16384 x 257 x 128)
// Tile: 64 rows x 128 cols, 256 threads, 4x8 per thread via f32x2 pairs
// (acc pairs along h). A duplicated in shared for broadcast-pair loads.
// K-chunks of 16 (16 chunks) + final single column (log_eps).
// =============================================================================
__global__ __launch_bounds__(256) void k1_proj(
    const float* __restrict__ f, const float* __restrict__ le,
    const float* __restrict__ Wq, const float* __restrict__ Wk)
{
    __shared__ float Ad[16][128];   // duplicated A: Ad[k][2n]=Ad[k][2n+1]=A[k][n]
    __shared__ float Bs[16][132];   // [k][h]

    const int t  = threadIdx.x;
    const int ty = t >> 4;          // 0..15 -> rows ty*4..ty*4+3
    const int tx = t & 15;          // 0..15 -> cols tx*8..tx*8+7
    const int rowBase = blockIdx.x * 64;      // global row (b*N + n)
    const int b = rowBase / NN;

    unsigned long long acc[4][4];   // [i][jp] -> cols {2jp, 2jp+1}
    #pragma unroll
    for (int i = 0; i < 4; i++)
        #pragma unroll
        for (int j = 0; j < 4; j++) acc[i][j] = 0ull;

    for (int kc = 0; kc < 16; kc++) {
        const int k0 = kc * 16;
        __syncthreads();
        // A: 64 n x 16 k  (256 float4 = 1 per thread), store duplicated
        {
            int r  = t >> 2;        // 0..63
            int c4 = t & 3;         // 0..3 -> k offset c4*4
            float4 v = *(const float4*)&f[(size_t)(rowBase + r) * DF + k0 + c4 * 4];
            float2 d;
            d.x = v.x; d.y = v.x; *(float2*)&Ad[c4*4+0][2*r] = d;
            d.x = v.y; d.y = v.y; *(float2*)&Ad[c4*4+1][2*r] = d;
            d.x = v.z; d.y = v.z; *(float2*)&Ad[c4*4+2][2*r] = d;
            d.x = v.w; d.y = v.w; *(float2*)&Ad[c4*4+3][2*r] = d;
        }
        // B: 16 k x 128 h (512 float4, 2 per thread)
        #pragma unroll
        for (int it = 0; it < 2; it++) {
            int idx = it * 256 + t;
            int kk  = idx >> 5;     // 0..15
            int h4  = idx & 31;     // 0..31
            int c   = k0 + kk;
            int h   = h4 * 4;
            float4 v = (h < 64) ? *(const float4*)&Wq[c * DH + h]
                                : *(const float4*)&Wk[c * DH + (h - 64)];
            *(float4*)&Bs[kk][h] = v;
        }
        __syncthreads();
        #pragma unroll
        for (int kk = 0; kk < 16; kk++) {
            ulonglong2 a01 = *(const ulonglong2*)&Ad[kk][ty * 8 + 0];
            ulonglong2 a23 = *(const ulonglong2*)&Ad[kk][ty * 8 + 4];
            ulonglong2 b01 = *(const ulonglong2*)&Bs[kk][tx * 8 + 0];
            ulonglong2 b23 = *(const ulonglong2*)&Bs[kk][tx * 8 + 4];
            unsigned long long aa[4] = {a01.x, a01.y, a23.x, a23.y};
            unsigned long long bb[4] = {b01.x, b01.y, b23.x, b23.y};
            #pragma unroll
            for (int i = 0; i < 4; i++)
                #pragma unroll
                for (int j = 0; j < 4; j++) ffma2(acc[i][j], aa[i], bb[j]);
        }
    }

    // final fc column (index 256) = log_eps[b]
    __syncthreads();
    {
        float lv = le[b];
        if (t < 64) { float2 d; d.x = lv; d.y = lv; *(float2*)&Ad[0][2 * t] = d; }
        if (t < 32) {
            int h = t * 4;
            float4 v = (h < 64) ? *(const float4*)&Wq[256 * DH + h]
                                : *(const float4*)&Wk[256 * DH + (h - 64)];
            *(float4*)&Bs[0][h] = v;
        }
    }
    __syncthreads();
    {
        ulonglong2 a01 = *(const ulonglong2*)&Ad[0][ty * 8 + 0];
        ulonglong2 a23 = *(const ulonglong2*)&Ad[0][ty * 8 + 4];
        ulonglong2 b01 = *(const ulonglong2*)&Bs[0][tx * 8 + 0];
        ulonglong2 b23 = *(const ulonglong2*)&Bs[0][tx * 8 + 4];
        unsigned long long aa[4] = {a01.x, a01.y, a23.x, a23.y};
        unsigned long long bb[4] = {b01.x, b01.y, b23.x, b23.y};
        #pragma unroll
        for (int i = 0; i < 4; i++)
            #pragma unroll
            for (int j = 0; j < 4; j++) ffma2(acc[i][j], aa[i], bb[j]);
    }

    #pragma unroll
    for (int i = 0; i < 4; i++) {
        int row = rowBase + ty * 4 + i;
        float o[8];
        #pragma unroll
        for (int j = 0; j < 4; j++) {
            float2 p = u2f(acc[i][j]);
            o[2 * j] = p.x; o[2 * j + 1] = p.y;
        }
        float4 o0 = {o[0], o[1], o[2], o[3]};
        float4 o1 = {o[4], o[5], o[6], o[7]};
        *(float4*)&g_QK[(size_t)row * QKW + tx * 8]     = o0;
        *(float4*)&g_QK[(size_t)row * QKW + tx * 8 + 4] = o1;
    }
}

// =============================================================================
// K2: E[n,m] = exp( q_n . k_m / 8 )  written (unnormalized) into pi output,
//     plus deterministic per-(b, n-tile) column-sum partials.
// Tile: 128 n x 128 m, 256 threads, 8x8 per thread via f32x2 pairs along m.
// K=64 in four 16-chunks.  grid (mt=16, nt=16, b=8)
// =============================================================================
__global__ __launch_bounds__(256) void k2_logits(float* __restrict__ pi)
{
    __shared__ float Ad[16][256];   // duplicated q^T: Ad[k][2n]=Ad[k][2n+1]=q[n][k]
    __shared__ float Bs[16][132];   // k^T: [k][m]

    const int t  = threadIdx.x;
    const int ty = t >> 4;          // rows ty*8..+7
    const int tx = t & 15;          // cols tx*8..+7
    const int m0 = blockIdx.x * 128;
    const int n0 = blockIdx.y * 128;
    const int b  = blockIdx.z;
    const float* __restrict__ Q = g_QK + (size_t)b * NN * QKW;

    unsigned long long acc[8][4];   // [i][jp] -> cols {2jp, 2jp+1}
    #pragma unroll
    for (int i = 0; i < 8; i++)
        #pragma unroll
        for (int j = 0; j < 4; j++) acc[i][j] = 0ull;

    for (int kc = 0; kc < 4; kc++) {
        __syncthreads();
        #pragma unroll
        for (int it = 0; it < 2; it++) {
            int idx = it * 256 + t;
            int r   = idx >> 2;     // 0..127
            int c4  = idx & 3;      // k offset c4*4
            float4 v = *(const float4*)&Q[(size_t)(n0 + r) * QKW + kc * 16 + c4 * 4];
            float2 d;
            d.x = v.x; d.y = v.x; *(float2*)&Ad[c4*4+0][2*r] = d;
            d.x = v.y; d.y = v.y; *(float2*)&Ad[c4*4+1][2*r] = d;
            d.x = v.z; d.y = v.z; *(float2*)&Ad[c4*4+2][2*r] = d;
            d.x = v.w; d.y = v.w; *(float2*)&Ad[c4*4+3][2*r] = d;
            float4 w = *(const float4*)&Q[(size_t)(m0 + r) * QKW + 64 + kc * 16 + c4 * 4];
            Bs[c4*4+0][r] = w.x;
            Bs[c4*4+1][r] = w.y;
            Bs[c4*4+2][r] = w.z;
            Bs[c4*4+3][r] = w.w;
        }
        __syncthreads();
        #pragma unroll
        for (int kk = 0; kk < 16; kk++) {
            ulonglong2 a01 = *(const ulonglong2*)&Ad[kk][ty * 16 + 0];
            ulonglong2 a23 = *(const ulonglong2*)&Ad[kk][ty * 16 + 4];
            ulonglong2 a45 = *(const ulonglong2*)&Ad[kk][ty * 16 + 8];
            ulonglong2 a67 = *(const ulonglong2*)&Ad[kk][ty * 16 + 12];
            ulonglong2 b01 = *(const ulonglong2*)&Bs[kk][tx * 8 + 0];
            ulonglong2 b23 = *(const ulonglong2*)&Bs[kk][tx * 8 + 4];
            unsigned long long aa[8] = {a01.x, a01.y, a23.x, a23.y,
                                        a45.x, a45.y, a67.x, a67.y};
            unsigned long long bb[4] = {b01.x, b01.y, b23.x, b23.y};
            #pragma unroll
            for (int i = 0; i < 8; i++)
                #pragma unroll
                for (int j = 0; j < 4; j++) ffma2(acc[i][j], aa[i], bb[j]);
        }
    }

    // exp + store + per-thread column sums
    float csj[8];
    #pragma unroll
    for (int j = 0; j < 8; j++) csj[j] = 0.f;
    const size_t piBase = (size_t)b * NN * NN;
    #pragma unroll
    for (int i = 0; i < 8; i++) {
        int n = n0 + ty * 8 + i;
        float ev[8];
        #pragma unroll
        for (int j = 0; j < 4; j++) {
            float2 p = u2f(acc[i][j]);
            ev[2 * j]     = __expf(p.x * 0.125f);
            ev[2 * j + 1] = __expf(p.y * 0.125f);
        }
        #pragma unroll
        for (int j = 0; j < 8; j++) csj[j] += ev[j];
        float4 o0 = {ev[0], ev[1], ev[2], ev[3]};
        float4 o1 = {ev[4], ev[5], ev[6], ev[7]};
        *(float4*)&pi[piBase + (size_t)n * NN + m0 + tx * 8]     = o0;
        *(float4*)&pi[piBase + (size_t)n * NN + m0 + tx * 8 + 4] = o1;
    }

    // reduce column sums across the 16 ty rows (deterministic, no atomics)
    __syncthreads();
    float* red = &Ad[0][0];   // 16*128 floats fit easily
    #pragma unroll
    for (int j = 0; j < 8; j++) red[ty * 128 + tx * 8 + j] = csj[j];
    __syncthreads();
    if (t < 128) {
        float s = 0.f;
        #pragma unroll
        for (int r = 0; r < 16; r++) s += red[r * 128 + t];
        g_cs_part[(size_t)(b * 16 + blockIdx.y) * NN + m0 + t] = s;
    }
}

// K2b: colsum[b][m] = sum over 16 n-tiles
__global__ void k2b_reduce()
{
    int i = blockIdx.x * 256 + threadIdx.x;      // 0 .. B*N-1
    int b = i >> 11, m = i & (NN - 1);
    float s = 0.f;
    #pragma unroll
    for (int nt = 0; nt < 16; nt++) s += g_cs_part[(size_t)(b * 16 + nt) * NN + m];
    g_cs[i] = s;
}

// =============================================================================
// K3: normalize pi in place (pi = e/colsum/N) and accumulate y partials
//     y[b,m,d] = sum_n (e/colsum) * x[n,d].  grid (mt=8, nc=16, b=8), 256 thr.
// Batched loads (MLP=8) + streaming cache hints + x broadcast via smem.
// =============================================================================
__global__ __launch_bounds__(256) void k3_norm(
    const float* __restrict__ x, float* __restrict__ pi)
{
    __shared__ float xs[128 * 3];
    const int t  = threadIdx.x;
    const int m  = blockIdx.x * 256 + t;
    const int nc = blockIdx.y;
    const int b  = blockIdx.z;
    const float* xb = x + (size_t)b * NN * 3 + (size_t)(nc * 128) * 3;
    // strided fill: 384 elements, 256 threads
    for (int i = t; i < 128 * 3; i += 256) xs[i] = xb[i];
    const float inv  = 1.0f / g_cs[(size_t)b * NN + m];
    const float invN = 1.0f / (float)NN;
    __syncthreads();

    float a0 = 0.f, a1 = 0.f, a2 = 0.f;
    size_t base = (size_t)b * NN * NN + (size_t)(nc * 128) * NN + m;
    #pragma unroll 2
    for (int nb = 0; nb < 16; nb++) {
        float* pp = pi + base + (size_t)(nb * 8) * NN;
        float e[8];
        #pragma unroll
        for (int u = 0; u < 8; u++) e[u] = __ldcs(pp + (size_t)u * NN);
        #pragma unroll
        for (int u = 0; u < 8; u++) {
            float p = e[u] * inv;
            __stcs(pp + (size_t)u * NN, p * invN);
            int n = nb * 8 + u;
            a0 += p * xs[n * 3 + 0];
            a1 += p * xs[n * 3 + 1];
            a2 += p * xs[n * 3 + 2];
        }
    }
    size_t yi = ((size_t)(b * 16 + nc) * NN + m) * 3;
    g_y_part[yi + 0] = a0;
    g_y_part[yi + 1] = a1;
    g_y_part[yi + 2] = a2;
}

// K4: reduce y partials into d_out's y region
__global__ void k4_reduce(float* __restrict__ y)
{
    int i = blockIdx.x * 256 + threadIdx.x;      // 0 .. 49151
    int b = i / (NN * 3);
    int r = i - b * (NN * 3);                    // m*3 + d
    float s = 0.f;
    #pragma unroll
    for (int nc = 0; nc < 16; nc++)
        s += g_y_part[(size_t)(b * 16 + nc) * (NN * 3) + r];
    y[i] = s;
}

// =============================================================================
extern "C" void kernel_launch(void* const* d_in, const int* in_sizes, int n_in,
                              void* d_out, int out_size)
{
    const float* f  = (const float*)d_in[0];   // (B, N, 256)
    const float* x  = (const float*)d_in[1];   // (B, N, 3)
    const float* le = (const float*)d_in[2];   // (B,)
    const float* Wq = (const float*)d_in[3];   // (257, 64)
    const float* Wk = (const float*)d_in[4];   // (257, 64)

    float* out = (float*)d_out;
    float* y   = out;                          // (B, N, 3)  = 49152 floats
    float* pi  = out + (size_t)BB * NN * 3;    // (B, N, N)

    k1_proj<<<(BB * NN) / 64, 256>>>(f, le, Wq, Wk);
    k2_logits<<<dim3(16, 16, BB), 256>>>(pi);
    k2b_reduce<<<(BB * NN) / 256, 256>>>();
    k3_norm<<<dim3(8, 16, BB), 256>>>(x, pi);
    k4_reduce<<<(BB * NN * 3) / 256, 256>>>(y);
}

// round 12
// speedup vs baseline: 1.0156x; 1.0156x over previous
#include <cuda_runtime.h>
#include <cstdint>

// Problem constants
#define BB     8
#define NN     2048
#define DF     256     // d_feat
#define KF     257     // d_feat + 1
#define DH     64      // head dim
#define QKW    128     // q(64) | k(64) packed per row

// ---------------- scratch (__device__ globals; no allocation) ----------------
__device__ float g_QK[(size_t)BB * NN * QKW];          // 8 MB: [row][0..63]=q, [64..127]=k
__device__ float g_cs_part[(size_t)BB * 16 * NN];      // per-(b, n-tile) column-sum partials
__device__ float g_cs[(size_t)BB * NN];                // final column sums
__device__ float g_y_part[(size_t)BB * 16 * NN * 3];   // per-(b, n-chunk) y partials

// ---------------- tf32 helpers ----------------
__device__ __forceinline__ float tf32_rna(float x) {
    float r;
    asm("cvt.rna.tf32.f32 %0, %1;" : "=f"(r) : "f"(x));
    return r;
}
__device__ __forceinline__ void mma_16n8k8(float& c0, float& c1, float& c2, float& c3,
                                           uint32_t a0, uint32_t a1, uint32_t a2, uint32_t a3,
                                           uint32_t b0, uint32_t b1) {
    asm volatile(
        "mma.sync.aligned.m16n8k8.row.col.f32.tf32.tf32.f32 "
        "{%0,%1,%2,%3}, {%4,%5,%6,%7}, {%8,%9}, {%0,%1,%2,%3};"
        : "+f"(c0), "+f"(c1), "+f"(c2), "+f"(c3)
        : "r"(a0), "r"(a1), "r"(a2), "r"(a3), "r"(b0), "r"(b1));
}

// =============================================================================
// K1 (scalar SIMT, measured-good): fc = [f | log_eps] ; QK = fc @ [W_q | W_k]
// =============================================================================
__global__ __launch_bounds__(256) void k1_proj(
    const float* __restrict__ f, const float* __restrict__ le,
    const float* __restrict__ Wq, const float* __restrict__ Wk)
{
    __shared__ float As[32][68];    // [k][n]
    __shared__ float Bs[32][132];   // [k][h]

    const int t  = threadIdx.x;
    const int ty = t >> 4;
    const int tx = t & 15;
    const int rowBase = blockIdx.x * 64;
    const int b = rowBase / NN;

    float acc[4][8];
    #pragma unroll
    for (int i = 0; i < 4; i++)
        #pragma unroll
        for (int j = 0; j < 8; j++) acc[i][j] = 0.f;

    for (int kc = 0; kc < 9; kc++) {
        const int k0 = kc * 32;
        const int len = (KF - k0 < 32) ? (KF - k0) : 32;
        __syncthreads();
        if (len == 32) {
            #pragma unroll
            for (int it = 0; it < 2; it++) {
                int n  = (t >> 3) + it * 32;
                int kk = (t & 7) * 4;
                float4 v = *(const float4*)&f[(size_t)(rowBase + n) * DF + k0 + kk];
                As[kk + 0][n] = v.x; As[kk + 1][n] = v.y;
                As[kk + 2][n] = v.z; As[kk + 3][n] = v.w;
            }
            #pragma unroll
            for (int it = 0; it < 4; it++) {
                int kk = (t >> 5) + it * 8;
                int h  = (t & 31) * 4;
                int c  = k0 + kk;
                float4 v = (h < 64) ? *(const float4*)&Wq[c * DH + h]
                                    : *(const float4*)&Wk[c * DH + (h - 64)];
                Bs[kk][h + 0] = v.x; Bs[kk][h + 1] = v.y;
                Bs[kk][h + 2] = v.z; Bs[kk][h + 3] = v.w;
            }
        } else {
            float lv = le[b];
            for (int idx = t; idx < 32 * 64; idx += 256) {
                int kk = idx >> 6, n = idx & 63;
                As[kk][n] = (kk == 0) ? lv : 0.f;
            }
            if (t < 32) {
                int h = t * 4;
                float4 v = (h < 64) ? *(const float4*)&Wq[256 * DH + h]
                                    : *(const float4*)&Wk[256 * DH + (h - 64)];
                Bs[0][h + 0] = v.x; Bs[0][h + 1] = v.y;
                Bs[0][h + 2] = v.z; Bs[0][h + 3] = v.w;
            }
        }
        __syncthreads();
        #pragma unroll 8
        for (int kk = 0; kk < 32; kk++) {
            float4 av = *(const float4*)&As[kk][ty * 4];
            float4 b0 = *(const float4*)&Bs[kk][tx * 8];
            float4 b1 = *(const float4*)&Bs[kk][tx * 8 + 4];
            float a[4]  = {av.x, av.y, av.z, av.w};
            float bv[8] = {b0.x, b0.y, b0.z, b0.w, b1.x, b1.y, b1.z, b1.w};
            #pragma unroll
            for (int i = 0; i < 4; i++)
                #pragma unroll
                for (int j = 0; j < 8; j++) acc[i][j] += a[i] * bv[j];
        }
    }
    #pragma unroll
    for (int i = 0; i < 4; i++) {
        int row = rowBase + ty * 4 + i;
        float4 o0 = {acc[i][0], acc[i][1], acc[i][2], acc[i][3]};
        float4 o1 = {acc[i][4], acc[i][5], acc[i][6], acc[i][7]};
        *(float4*)&g_QK[(size_t)row * QKW + tx * 8]     = o0;
        *(float4*)&g_QK[(size_t)row * QKW + tx * 8 + 4] = o1;
    }
}

// =============================================================================
// K2 (mma.sync tf32, 3xTF32): E[n,m] = exp(q_n.k_m/8) -> pi (unnormalized)
// + per-(b, n-tile) column-sum partials.
// Tile 128n x 128m, K=64, 256 threads (8 warps: 4n x 2m), each warp 32x64.
// Dynamic smem (floats): A_hi[128][68] | A_lo | B_hi | B_lo  (139,264 B).
// Epilogue stages exp values in S[128][136] (overlays A region).
// =============================================================================
#define K2_SMEM_BYTES (4 * 128 * 68 * 4)
#define STR 68
#define A_HI 0
#define A_LO (128 * 68)
#define B_HI (2 * 128 * 68)
#define B_LO (3 * 128 * 68)
#define S_STR 136
#define CS2  (2 * 128 * 68)     // 256-float half-colsum scratch (B region, post-MMA)

__global__ __launch_bounds__(256, 1) void k2_tc(float* __restrict__ pi)
{
    extern __shared__ float sm[];
    const int t    = threadIdx.x;
    const int wid  = t >> 5;
    const int lane = t & 31;
    const int g    = lane >> 2;       // 0..7 (group)
    const int c4   = lane & 3;        // 0..3
    const int m0   = blockIdx.x * 128;
    const int n0   = blockIdx.y * 128;
    const int b    = blockIdx.z;
    const float* __restrict__ Q = g_QK + (size_t)b * NN * QKW;

    // ---- load + tf32 hi/lo split: thread t handles one row (Q for t<128, K else)
    {
        const int r = t & 127;
        const float* src = (t < 128) ? &Q[(size_t)(n0 + r) * QKW]
                                     : &Q[(size_t)(m0 + r) * QKW + 64];
        float* dhi = (t < 128) ? &sm[A_HI + r * STR] : &sm[B_HI + r * STR];
        float* dlo = (t < 128) ? &sm[A_LO + r * STR] : &sm[B_LO + r * STR];
        #pragma unroll
        for (int gg = 0; gg < 16; gg++) {
            float4 v = *(const float4*)&src[gg * 4];
            float4 hi, lo;
            hi.x = tf32_rna(v.x); lo.x = tf32_rna(v.x - hi.x);
            hi.y = tf32_rna(v.y); lo.y = tf32_rna(v.y - hi.y);
            hi.z = tf32_rna(v.z); lo.z = tf32_rna(v.z - hi.z);
            hi.w = tf32_rna(v.w); lo.w = tf32_rna(v.w - hi.w);
            *(float4*)&dhi[gg * 4] = hi;
            *(float4*)&dlo[gg * 4] = lo;
        }
    }
    __syncthreads();

    // ---- mainloop: 3 passes (hi*hi, lo*hi, hi*lo) x 8 k-steps x 16 tiles ----
    const int warpN = wid >> 1;            // 0..3 -> n base warpN*32
    const int warpM = wid & 1;             // 0..1 -> m base warpM*64
    const int nbase = warpN * 32;
    const int mbase = warpM * 64;

    float acc[2][8][4];
    #pragma unroll
    for (int mi = 0; mi < 2; mi++)
        #pragma unroll
        for (int nj = 0; nj < 8; nj++)
            #pragma unroll
            for (int c = 0; c < 4; c++) acc[mi][nj][c] = 0.f;

    #pragma unroll
    for (int p = 0; p < 3; p++) {
        const float* Abuf = &sm[(p == 1) ? A_LO : A_HI];
        const float* Bbuf = &sm[(p == 2) ? B_LO : B_HI];
        #pragma unroll
        for (int ks = 0; ks < 8; ks++) {
            const int k0 = ks * 8;
            uint32_t a[2][4], bb[8][2];
            #pragma unroll
            for (int mi = 0; mi < 2; mi++) {
                const float* ap = &Abuf[(nbase + mi * 16 + g) * STR + k0 + c4];
                a[mi][0] = __float_as_uint(ap[0]);
                a[mi][1] = __float_as_uint(ap[8 * STR]);
                a[mi][2] = __float_as_uint(ap[4]);
                a[mi][3] = __float_as_uint(ap[8 * STR + 4]);
            }
            #pragma unroll
            for (int nj = 0; nj < 8; nj++) {
                const float* bp = &Bbuf[(mbase + nj * 8 + g) * STR + k0 + c4];
                bb[nj][0] = __float_as_uint(bp[0]);
                bb[nj][1] = __float_as_uint(bp[4]);
            }
            #pragma unroll
            for (int mi = 0; mi < 2; mi++)
                #pragma unroll
                for (int nj = 0; nj < 8; nj++)
                    mma_16n8k8(acc[mi][nj][0], acc[mi][nj][1],
                               acc[mi][nj][2], acc[mi][nj][3],
                               a[mi][0], a[mi][1], a[mi][2], a[mi][3],
                               bb[nj][0], bb[nj][1]);
        }
    }
    __syncthreads();   // done reading A/B smem; S overlays A region

    // ---- exp + stage into S[128][136] ----
    #pragma unroll
    for (int mi = 0; mi < 2; mi++) {
        const int nr0 = nbase + mi * 16 + g;
        #pragma unroll
        for (int nj = 0; nj < 8; nj++) {
            const int mc = mbase + nj * 8 + 2 * c4;
            float e0 = __expf(acc[mi][nj][0] * 0.125f);
            float e1 = __expf(acc[mi][nj][1] * 0.125f);
            float e2 = __expf(acc[mi][nj][2] * 0.125f);
            float e3 = __expf(acc[mi][nj][3] * 0.125f);
            *(float2*)&sm[nr0 * S_STR + mc]       = make_float2(e0, e1);
            *(float2*)&sm[(nr0 + 8) * S_STR + mc] = make_float2(e2, e3);
        }
    }
    __syncthreads();

    // ---- coalesced pi stores from S (each warp streams full rows) ----
    const size_t piBase = (size_t)b * NN * NN;
    #pragma unroll
    for (int i = 0; i < 16; i++) {
        int row = wid + i * 8;
        float4 v = *(const float4*)&sm[row * S_STR + lane * 4];
        *(float4*)&pi[piBase + (size_t)(n0 + row) * NN + m0 + lane * 4] = v;
    }

    // ---- deterministic column sums ----
    {
        const int col = t & 127, half = t >> 7;
        float s = 0.f;
        #pragma unroll 8
        for (int n = 0; n < 64; n++) s += sm[(half * 64 + n) * S_STR + col];
        sm[CS2 + half * 128 + col] = s;
    }
    __syncthreads();
    if (t < 128) {
        float s = sm[CS2 + t] + sm[CS2 + 128 + t];
        g_cs_part[(size_t)(b * 16 + blockIdx.y) * NN + m0 + t] = s;
    }
}

// K2b: colsum[b][m] = sum over 16 n-tiles
__global__ void k2b_reduce()
{
    int i = blockIdx.x * 256 + threadIdx.x;
    int b = i >> 11, m = i & (NN - 1);
    float s = 0.f;
    #pragma unroll
    for (int nt = 0; nt < 16; nt++) s += g_cs_part[(size_t)(b * 16 + nt) * NN + m];
    g_cs[i] = s;
}

// =============================================================================
// K3 (measured-good R10): normalize pi in place + y partials
// =============================================================================
__global__ __launch_bounds__(256) void k3_norm(
    const float* __restrict__ x, float* __restrict__ pi)
{
    __shared__ float xs[128 * 3];
    const int t  = threadIdx.x;
    const int m  = blockIdx.x * 256 + t;
    const int nc = blockIdx.y;
    const int b  = blockIdx.z;
    const float* xb = x + (size_t)b * NN * 3 + (size_t)(nc * 128) * 3;
    for (int i = t; i < 128 * 3; i += 256) xs[i] = xb[i];
    const float inv  = 1.0f / g_cs[(size_t)b * NN + m];
    const float invN = 1.0f / (float)NN;
    __syncthreads();

    float a0 = 0.f, a1 = 0.f, a2 = 0.f;
    size_t base = (size_t)b * NN * NN + (size_t)(nc * 128) * NN + m;
    #pragma unroll 2
    for (int nb = 0; nb < 16; nb++) {
        float* pp = pi + base + (size_t)(nb * 8) * NN;
        float e[8];
        #pragma unroll
        for (int u = 0; u < 8; u++) e[u] = __ldcs(pp + (size_t)u * NN);
        #pragma unroll
        for (int u = 0; u < 8; u++) {
            float p = e[u] * inv;
            __stcs(pp + (size_t)u * NN, p * invN);
            int n = nb * 8 + u;
            a0 += p * xs[n * 3 + 0];
            a1 += p * xs[n * 3 + 1];
            a2 += p * xs[n * 3 + 2];
        }
    }
    size_t yi = ((size_t)(b * 16 + nc) * NN + m) * 3;
    g_y_part[yi + 0] = a0;
    g_y_part[yi + 1] = a1;
    g_y_part[yi + 2] = a2;
}

// K4: reduce y partials into d_out's y region
__global__ void k4_reduce(float* __restrict__ y)
{
    int i = blockIdx.x * 256 + threadIdx.x;
    int b = i / (NN * 3);
    int r = i - b * (NN * 3);
    float s = 0.f;
    #pragma unroll
    for (int nc = 0; nc < 16; nc++)
        s += g_y_part[(size_t)(b * 16 + nc) * (NN * 3) + r];
    y[i] = s;
}

// =============================================================================
extern "C" void kernel_launch(void* const* d_in, const int* in_sizes, int n_in,
                              void* d_out, int out_size)
{
    const float* f  = (const float*)d_in[0];   // (B, N, 256)
    const float* x  = (const float*)d_in[1];   // (B, N, 3)
    const float* le = (const float*)d_in[2];   // (B,)
    const float* Wq = (const float*)d_in[3];   // (257, 64)
    const float* Wk = (const float*)d_in[4];   // (257, 64)

    float* out = (float*)d_out;
    float* y   = out;                          // (B, N, 3)
    float* pi  = out + (size_t)BB * NN * 3;    // (B, N, N)

    static int smem_set = 0;
    if (!smem_set) {
        cudaFuncSetAttribute(k2_tc, cudaFuncAttributeMaxDynamicSharedMemorySize,
                             K2_SMEM_BYTES);
        smem_set = 1;
    }

    k1_proj<<<(BB * NN) / 64, 256>>>(f, le, Wq, Wk);
    k2_tc<<<dim3(16, 16, BB), 256, K2_SMEM_BYTES>>>(pi);
    k2b_reduce<<<(BB * NN) / 256, 256>>>();
    k3_norm<<<dim3(8, 16, BB), 256>>>(x, pi);
    k4_reduce<<<(BB * NN * 3) / 256, 256>>>(y);
}

// round 15
// speedup vs baseline: 1.1207x; 1.1035x over previous
#include <cuda_runtime.h>
#include <cuda_bf16.h>
#include <cstdint>

// Problem constants
#define BB     8
#define NN     2048
#define DF     256     // d_feat
#define KF     257     // d_feat + 1
#define DH     64      // head dim
#define QKW    128     // q(64) | k(64) packed per row

// ---------------- scratch (__device__ globals; no allocation) ----------------
__device__ float g_QK[(size_t)BB * NN * QKW];          // [row][0..63]=q, [64..127]=k
__device__ float g_cs_part[(size_t)BB * 16 * NN];      // per-(b, n-tile) column-sum partials
__device__ float g_cs[(size_t)BB * NN];                // final column sums
__device__ float g_y_part[(size_t)BB * 16 * NN * 3];   // per-(b, n-chunk) y partials

// ---------------- mma helpers ----------------
__device__ __forceinline__ uint32_t smem_u32(const void* p) {
    uint32_t a;
    asm("{ .reg .u64 t; cvta.to.shared.u64 t, %1; cvt.u32.u64 %0, t; }"
        : "=r"(a) : "l"(p));
    return a;
}
__device__ __forceinline__ void ldsm_x4(uint32_t& r0, uint32_t& r1,
                                        uint32_t& r2, uint32_t& r3, uint32_t addr) {
    asm volatile("ldmatrix.sync.aligned.m8n8.x4.shared.b16 {%0,%1,%2,%3}, [%4];"
                 : "=r"(r0), "=r"(r1), "=r"(r2), "=r"(r3) : "r"(addr));
}
__device__ __forceinline__ void mma_bf16(float& c0, float& c1, float& c2, float& c3,
                                         uint32_t a0, uint32_t a1, uint32_t a2, uint32_t a3,
                                         uint32_t b0, uint32_t b1) {
    asm volatile(
        "mma.sync.aligned.m16n8k16.row.col.f32.bf16.bf16.f32 "
        "{%0,%1,%2,%3}, {%4,%5,%6,%7}, {%8,%9}, {%0,%1,%2,%3};"
        : "+f"(c0), "+f"(c1), "+f"(c2), "+f"(c3)
        : "r"(a0), "r"(a1), "r"(a2), "r"(a3), "r"(b0), "r"(b1));
}
__device__ __forceinline__ uint32_t pack_bf2(__nv_bfloat16 lo, __nv_bfloat16 hi) {
    __nv_bfloat162 v; v.x = lo; v.y = hi;
    return *(uint32_t*)&v;
}

// =============================================================================
// K1 (scalar, measured-good): fc = [f | log_eps] ; QK = fc @ [W_q | W_k]
// =============================================================================
__global__ __launch_bounds__(256) void k1_proj(
    const float* __restrict__ f, const float* __restrict__ le,
    const float* __restrict__ Wq, const float* __restrict__ Wk)
{
    __shared__ float As[32][68];
    __shared__ float Bs[32][132];

    const int t  = threadIdx.x;
    const int ty = t >> 4;
    const int tx = t & 15;
    const int rowBase = blockIdx.x * 64;
    const int b = rowBase / NN;

    float acc[4][8];
    #pragma unroll
    for (int i = 0; i < 4; i++)
        #pragma unroll
        for (int j = 0; j < 8; j++) acc[i][j] = 0.f;

    for (int kc = 0; kc < 9; kc++) {
        const int k0 = kc * 32;
        const int len = (KF - k0 < 32) ? (KF - k0) : 32;
        __syncthreads();
        if (len == 32) {
            #pragma unroll
            for (int it = 0; it < 2; it++) {
                int n  = (t >> 3) + it * 32;
                int kk = (t & 7) * 4;
                float4 v = *(const float4*)&f[(size_t)(rowBase + n) * DF + k0 + kk];
                As[kk + 0][n] = v.x; As[kk + 1][n] = v.y;
                As[kk + 2][n] = v.z; As[kk + 3][n] = v.w;
            }
            #pragma unroll
            for (int it = 0; it < 4; it++) {
                int kk = (t >> 5) + it * 8;
                int h  = (t & 31) * 4;
                int c  = k0 + kk;
                float4 v = (h < 64) ? *(const float4*)&Wq[c * DH + h]
                                    : *(const float4*)&Wk[c * DH + (h - 64)];
                Bs[kk][h + 0] = v.x; Bs[kk][h + 1] = v.y;
                Bs[kk][h + 2] = v.z; Bs[kk][h + 3] = v.w;
            }
        } else {
            float lv = le[b];
            for (int idx = t; idx < 32 * 64; idx += 256) {
                int kk = idx >> 6, n = idx & 63;
                As[kk][n] = (kk == 0) ? lv : 0.f;
            }
            if (t < 32) {
                int h = t * 4;
                float4 v = (h < 64) ? *(const float4*)&Wq[256 * DH + h]
                                    : *(const float4*)&Wk[256 * DH + (h - 64)];
                Bs[0][h + 0] = v.x; Bs[0][h + 1] = v.y;
                Bs[0][h + 2] = v.z; Bs[0][h + 3] = v.w;
            }
        }
        __syncthreads();
        #pragma unroll 8
        for (int kk = 0; kk < 32; kk++) {
            float4 av = *(const float4*)&As[kk][ty * 4];
            float4 b0 = *(const float4*)&Bs[kk][tx * 8];
            float4 b1 = *(const float4*)&Bs[kk][tx * 8 + 4];
            float a[4]  = {av.x, av.y, av.z, av.w};
            float bv[8] = {b0.x, b0.y, b0.z, b0.w, b1.x, b1.y, b1.z, b1.w};
            #pragma unroll
            for (int i = 0; i < 4; i++)
                #pragma unroll
                for (int j = 0; j < 8; j++) acc[i][j] += a[i] * bv[j];
        }
    }
    #pragma unroll
    for (int i = 0; i < 4; i++) {
        int row = rowBase + ty * 4 + i;
        float4 o0 = {acc[i][0], acc[i][1], acc[i][2], acc[i][3]};
        float4 o1 = {acc[i][4], acc[i][5], acc[i][6], acc[i][7]};
        *(float4*)&g_QK[(size_t)row * QKW + tx * 8]     = o0;
        *(float4*)&g_QK[(size_t)row * QKW + tx * 8 + 4] = o1;
    }
}

// =============================================================================
// K2 (bf16 mma.sync, 3-term split): E = exp(q.k/8) -> pi + colsum partials.
// 128n x 128m tile, K=64, 256 threads (8 warps: 4n x 2m), warp 32n x 64m.
// Dyn smem bf16: A_hi|A_lo|B_hi|B_lo, each [128][72] (144B rows) = 73728 B.
// Epilogue stages exp in float S[128][136] overlay + CS scratch.
// =============================================================================
#define K2_SMEM_BYTES 73728
#define RSTR 72            // bf16 elems per row (144 B)
#define AB_HI 0
#define AB_LO 18432
#define BB_HI 36864
#define BB_LO 55296
#define S_STR 136
#define CS2F  17408        // float offset of 256-float colsum scratch

__global__ __launch_bounds__(256, 1) void k2_tc(float* __restrict__ pi)
{
    extern __shared__ char sm[];
    float* smf = (float*)sm;
    const int t    = threadIdx.x;
    const int wid  = t >> 5;
    const int lane = t & 31;
    const int g    = lane >> 2;
    const int c4   = lane & 3;
    const int m0   = blockIdx.x * 128;
    const int n0   = blockIdx.y * 128;
    const int b    = blockIdx.z;
    const float* __restrict__ Q = g_QK + (size_t)b * NN * QKW;

    // ---- load + bf16 hi/lo split: thread t -> one row (Q for t<128, K else)
    {
        const int r = t & 127;
        const float* src = (t < 128) ? &Q[(size_t)(n0 + r) * QKW]
                                     : &Q[(size_t)(m0 + r) * QKW + 64];
        char* dhi = sm + ((t < 128) ? AB_HI : BB_HI) + r * 144;
        char* dlo = sm + ((t < 128) ? AB_LO : BB_LO) + r * 144;
        #pragma unroll
        for (int gg = 0; gg < 16; gg++) {
            float4 v = *(const float4*)&src[gg * 4];
            __nv_bfloat16 hx = __float2bfloat16(v.x);
            __nv_bfloat16 hy = __float2bfloat16(v.y);
            __nv_bfloat16 hz = __float2bfloat16(v.z);
            __nv_bfloat16 hw = __float2bfloat16(v.w);
            __nv_bfloat16 lx = __float2bfloat16(v.x - __bfloat162float(hx));
            __nv_bfloat16 ly = __float2bfloat16(v.y - __bfloat162float(hy));
            __nv_bfloat16 lz = __float2bfloat16(v.z - __bfloat162float(hz));
            __nv_bfloat16 lw = __float2bfloat16(v.w - __bfloat162float(hw));
            uint2 hp = make_uint2(pack_bf2(hx, hy), pack_bf2(hz, hw));
            uint2 lp = make_uint2(pack_bf2(lx, ly), pack_bf2(lz, lw));
            *(uint2*)(dhi + gg * 8) = hp;
            *(uint2*)(dlo + gg * 8) = lp;
        }
    }
    __syncthreads();

    // ---- mainloop: 3 passes (hi*hi, lo*hi, hi*lo) x 4 k-steps x 16 mma ----
    const int warpN = wid >> 1;
    const int warpM = wid & 1;
    const int nbase = warpN * 32;
    const int mbase = warpM * 64;
    const int lane15 = lane & 15;
    const int kby    = (lane >> 4) * 16;   // byte offset of k-half (8 bf16)

    float acc[2][8][4];
    #pragma unroll
    for (int mi = 0; mi < 2; mi++)
        #pragma unroll
        for (int nj = 0; nj < 8; nj++)
            #pragma unroll
            for (int c = 0; c < 4; c++) acc[mi][nj][c] = 0.f;

    #pragma unroll
    for (int p = 0; p < 3; p++) {
        const char* Ab = sm + ((p == 1) ? AB_LO : AB_HI);
        const char* Bb = sm + ((p == 2) ? BB_LO : BB_HI);
        const uint32_t aBase = smem_u32(Ab + (nbase + lane15) * 144 + kby);
        const uint32_t bBase = smem_u32(Bb + (mbase + lane15) * 144 + kby);
        #pragma unroll
        for (int ks = 0; ks < 4; ks++) {
            const uint32_t ko = ks * 32;   // 16 bf16 = 32 bytes per k-step
            uint32_t a0[4], a1[4];
            ldsm_x4(a0[0], a0[1], a0[2], a0[3], aBase + ko);
            ldsm_x4(a1[0], a1[1], a1[2], a1[3], aBase + 16 * 144 + ko);
            #pragma unroll
            for (int jb = 0; jb < 4; jb++) {
                uint32_t r0, r1, r2, r3;
                ldsm_x4(r0, r1, r2, r3, bBase + jb * 16 * 144 + ko);
                // r0/r2 -> m-tile 2jb (b0,b1); r1/r3 -> m-tile 2jb+1
                mma_bf16(acc[0][2*jb][0], acc[0][2*jb][1], acc[0][2*jb][2], acc[0][2*jb][3],
                         a0[0], a0[1], a0[2], a0[3], r0, r2);
                mma_bf16(acc[0][2*jb+1][0], acc[0][2*jb+1][1], acc[0][2*jb+1][2], acc[0][2*jb+1][3],
                         a0[0], a0[1], a0[2], a0[3], r1, r3);
                mma_bf16(acc[1][2*jb][0], acc[1][2*jb][1], acc[1][2*jb][2], acc[1][2*jb][3],
                         a1[0], a1[1], a1[2], a1[3], r0, r2);
                mma_bf16(acc[1][2*jb+1][0], acc[1][2*jb+1][1], acc[1][2*jb+1][2], acc[1][2*jb+1][3],
                         a1[0], a1[1], a1[2], a1[3], r1, r3);
            }
        }
    }
    __syncthreads();   // done reading A/B smem; S overlays it

    // ---- exp + stage into S[128][136] ----
    #pragma unroll
    for (int mi = 0; mi < 2; mi++) {
        const int nr0 = nbase + mi * 16 + g;
        #pragma unroll
        for (int nj = 0; nj < 8; nj++) {
            const int mc = mbase + nj * 8 + 2 * c4;
            float e0 = __expf(acc[mi][nj][0] * 0.125f);
            float e1 = __expf(acc[mi][nj][1] * 0.125f);
            float e2 = __expf(acc[mi][nj][2] * 0.125f);
            float e3 = __expf(acc[mi][nj][3] * 0.125f);
            *(float2*)&smf[nr0 * S_STR + mc]       = make_float2(e0, e1);
            *(float2*)&smf[(nr0 + 8) * S_STR + mc] = make_float2(e2, e3);
        }
    }
    __syncthreads();

    // ---- coalesced pi stores from S ----
    const size_t piBase = (size_t)b * NN * NN;
    #pragma unroll
    for (int i = 0; i < 16; i++) {
        int row = wid + i * 8;
        float4 v = *(const float4*)&smf[row * S_STR + lane * 4];
        *(float4*)&pi[piBase + (size_t)(n0 + row) * NN + m0 + lane * 4] = v;
    }

    // ---- deterministic column sums ----
    {
        const int col = t & 127, half = t >> 7;
        float s = 0.f;
        #pragma unroll 8
        for (int n = 0; n < 64; n++) s += smf[(half * 64 + n) * S_STR + col];
        smf[CS2F + half * 128 + col] = s;
    }
    __syncthreads();
    if (t < 128) {
        float s = smf[CS2F + t] + smf[CS2F + 128 + t];
        g_cs_part[(size_t)(b * 16 + blockIdx.y) * NN + m0 + t] = s;
    }
}

// K2b: colsum[b][m] = sum over 16 n-tiles
__global__ void k2b_reduce()
{
    int i = blockIdx.x * 256 + threadIdx.x;
    int b = i >> 11, m = i & (NN - 1);
    float s = 0.f;
    #pragma unroll
    for (int nt = 0; nt < 16; nt++) s += g_cs_part[(size_t)(b * 16 + nt) * NN + m];
    g_cs[i] = s;
}

// =============================================================================
// K3 (R10 measured-good): normalize pi in place + y partials
// =============================================================================
__global__ __launch_bounds__(256) void k3_norm(
    const float* __restrict__ x, float* __restrict__ pi)
{
    __shared__ float xs[128 * 3];
    const int t  = threadIdx.x;
    const int m  = blockIdx.x * 256 + t;
    const int nc = blockIdx.y;
    const int b  = blockIdx.z;
    const float* xb = x + (size_t)b * NN * 3 + (size_t)(nc * 128) * 3;
    for (int i = t; i < 128 * 3; i += 256) xs[i] = xb[i];
    const float inv  = 1.0f / g_cs[(size_t)b * NN + m];
    const float invN = 1.0f / (float)NN;
    __syncthreads();

    float a0 = 0.f, a1 = 0.f, a2 = 0.f;
    size_t base = (size_t)b * NN * NN + (size_t)(nc * 128) * NN + m;
    #pragma unroll 2
    for (int nb = 0; nb < 16; nb++) {
        float* pp = pi + base + (size_t)(nb * 8) * NN;
        float e[8];
        #pragma unroll
        for (int u = 0; u < 8; u++) e[u] = __ldcs(pp + (size_t)u * NN);
        #pragma unroll
        for (int u = 0; u < 8; u++) {
            float p = e[u] * inv;
            __stcs(pp + (size_t)u * NN, p * invN);
            int n = nb * 8 + u;
            a0 += p * xs[n * 3 + 0];
            a1 += p * xs[n * 3 + 1];
            a2 += p * xs[n * 3 + 2];
        }
    }
    size_t yi = ((size_t)(b * 16 + nc) * NN + m) * 3;
    g_y_part[yi + 0] = a0;
    g_y_part[yi + 1] = a1;
    g_y_part[yi + 2] = a2;
}

// K4: reduce y partials into d_out's y region
__global__ void k4_reduce(float* __restrict__ y)
{
    int i = blockIdx.x * 256 + threadIdx.x;
    int b = i / (NN * 3);
    int r = i - b * (NN * 3);
    float s = 0.f;
    #pragma unroll
    for (int nc = 0; nc < 16; nc++)
        s += g_y_part[(size_t)(b * 16 + nc) * (NN * 3) + r];
    y[i] = s;
}

// =============================================================================
extern "C" void kernel_launch(void* const* d_in, const int* in_sizes, int n_in,
                              void* d_out, int out_size)
{
    const float* f  = (const float*)d_in[0];   // (B, N, 256)
    const float* x  = (const float*)d_in[1];   // (B, N, 3)
    const float* le = (const float*)d_in[2];   // (B,)
    const float* Wq = (const float*)d_in[3];   // (257, 64)
    const float* Wk = (const float*)d_in[4];   // (257, 64)

    float* out = (float*)d_out;
    float* y   = out;                          // (B, N, 3)
    float* pi  = out + (size_t)BB * NN * 3;    // (B, N, N)

    static int smem_set = 0;
    if (!smem_set) {
        cudaFuncSetAttribute(k2_tc, cudaFuncAttributeMaxDynamicSharedMemorySize,
                             K2_SMEM_BYTES);
        smem_set = 1;
    }

    k1_proj<<<(BB * NN) / 64, 256>>>(f, le, Wq, Wk);
    k2_tc<<<dim3(16, 16, BB), 256, K2_SMEM_BYTES>>>(pi);
    k2b_reduce<<<(BB * NN) / 256, 256>>>();
    k3_norm<<<dim3(8, 16, BB), 256>>>(x, pi);
    k4_reduce<<<(BB * NN * 3) / 256, 256>>>(y);
}